// round 10
// baseline (speedup 1.0000x reference)
#include <cuda_runtime.h>
#include <cstdint>

#define NE_MAX 100000
#define EMB 64
#define NREL 32

// Scratch (allocation-free rule: device globals)
__device__ __align__(16) float g_s[NE_MAX * EMB];      // sum of e * x per head
__device__ __align__(16) float g_denom[NE_MAX];        // sum of e per head
__device__ __align__(16) float g_cnt[NE_MAX];          // out-degree (constant)
__device__ __align__(16) float g_agg[NE_MAX * EMB];    // current agg
__device__ __align__(16) float g_q[NE_MAX * EMB];      // Q = agg @ q_w

static __device__ __forceinline__ unsigned long long pack2(float a, float b) {
    unsigned long long r;
    asm("mov.b64 %0, {%1,%2};" : "=l"(r) : "f"(a), "f"(b));
    return r;
}
static __device__ __forceinline__ void unpack2(unsigned long long v, float& a, float& b) {
    asm("mov.b64 {%0,%1}, %2;" : "=f"(a), "=f"(b) : "l"(v));
}
static __device__ __forceinline__ unsigned long long fma2(unsigned long long a,
                                                          unsigned long long b,
                                                          unsigned long long c) {
    unsigned long long d;
    asm("fma.rn.f32x2 %0, %1, %2, %3;" : "=l"(d) : "l"(a), "l"(b), "l"(c));
    return d;
}
static __device__ __forceinline__ float tanh_fast(float x) {
    float y;
    asm("tanh.approx.f32 %0, %1;" : "=f"(y) : "f"(x));
    return y;
}

// ---------------------------------------------------------------------------
__global__ void zero_sd_kernel(int N) {
    int i = blockIdx.x * blockDim.x + threadIdx.x;
    int st = gridDim.x * blockDim.x;
    float4* s4 = (float4*)g_s;
    int n4 = N * EMB / 4;
    for (int k = i; k < n4; k += st) s4[k] = make_float4(0.f, 0.f, 0.f, 0.f);
    float4* d4 = (float4*)g_denom;
    int m4 = (N + 3) / 4;
    for (int k = i; k < m4; k += st) d4[k] = make_float4(0.f, 0.f, 0.f, 0.f);
}

__global__ void zero_cnt_kernel(int N) {
    int i = blockIdx.x * blockDim.x + threadIdx.x;
    int st = gridDim.x * blockDim.x;
    float4* c4 = (float4*)g_cnt;
    int n4 = (N + 3) / 4;
    for (int k = i; k < n4; k += st) c4[k] = make_float4(0.f, 0.f, 0.f, 0.f);
}

__global__ void degree_kernel(const int* __restrict__ head, int E) {
    int i = blockIdx.x * blockDim.x + threadIdx.x;
    int st = gridDim.x * blockDim.x;
    for (; i < E; i += st) atomicAdd(&g_cnt[head[i]], 1.0f);
}

// ---------------------------------------------------------------------------
// dst[ent] = src[ent] @ W  (64x64), warp per entity, W register-resident.
__global__ void __launch_bounds__(256, 1) qproj_kernel(
    const float* __restrict__ src, float* __restrict__ dst,
    const float* __restrict__ W, int N) {
    __shared__ __align__(16) float sx[8][2 * EMB];
    int lane = threadIdx.x & 31, w = threadIdx.x >> 5;
    unsigned long long W2[EMB];
#pragma unroll
    for (int i = 0; i < EMB; i++) {
        float2 kv = *(const float2*)(W + i * EMB + 2 * lane);
        W2[i] = pack2(kv.x, kv.y);
    }
    int gw = blockIdx.x * 8 + w, nw = gridDim.x * 8;
    for (int ent = gw; ent < N; ent += nw) {
        float2 v = *(const float2*)(src + (size_t)ent * EMB + 2 * lane);
        *(float4*)(&sx[w][4 * lane]) = make_float4(v.x, v.x, v.y, v.y);
        __syncwarp();
        const ulonglong2* xd = (const ulonglong2*)sx[w];
        unsigned long long ya = 0ull, yb = 0ull;
#pragma unroll
        for (int i = 0; i < 32; i++) {
            ulonglong2 xv = xd[i];
            ya = fma2(xv.x, W2[2 * i], ya);
            yb = fma2(xv.y, W2[2 * i + 1], yb);
        }
        float y0a, y1a, y0b, y1b;
        unpack2(ya, y0a, y1a);
        unpack2(yb, y0b, y1b);
        __syncwarp();
        *(float2*)(dst + (size_t)ent * EMB + 2 * lane) =
            make_float2(y0a + y0b, y1a + y1b);
    }
}

// ---------------------------------------------------------------------------
// Fused edge pass, 4 edges per warp-iteration, software pipeline:
// indices loaded 2 groups ahead (int4), gathers 1 group ahead.
// x = rel*agg[tail]; y = tanh(x @ k_w); att = dot(Q[head], y); e = exp(att);
// scatter s[head] += e*x; denom[head] += e.
__global__ void __launch_bounds__(256, 1) edge_kernel(
    const float* __restrict__ agg, const float* __restrict__ Qm,
    const float* __restrict__ kw, const float* __restrict__ edge_emb,
    const int* __restrict__ head, const int* __restrict__ tail,
    const int* __restrict__ etype, int E) {
    __shared__ __align__(16) float srel[NREL * EMB];
    __shared__ __align__(16) float sx[2][8][4][2 * EMB];  // 32 KB
    int tid = threadIdx.x;
    for (int i = tid; i < NREL * EMB; i += 256) srel[i] = edge_emb[i];
    __syncthreads();
    int lane = tid & 31, w = tid >> 5;

    unsigned long long K2[EMB];
#pragma unroll
    for (int i = 0; i < EMB; i++) {
        float2 kv = *(const float2*)(kw + i * EMB + 2 * lane);
        K2[i] = pack2(kv.x, kv.y);
    }

    const int nwarp = gridDim.x * 8;
    const int ngrp = (E + 3) >> 2;
    const bool al4 = ((E & 3) == 0);

    int p = blockIdx.x * 8 + w;

    // current-group state
    int hc0, hc1, hc2, hc3, yc0, yc1, yc2, yc3;
    unsigned mc = 0;
    float2 a0, a1, a2c, a3, q0, q1, q2c, q3;
    // next-group indices
    int hn0, hn1, hn2, hn3, tn0, tn1, tn2, tn3, yn0, yn1, yn2, yn3;
    unsigned mn = 0;

#define LOAD_IDX(PG, H0, H1, H2, H3, T0, T1, T2, T3, Y0, Y1, Y2, Y3, M)       \
    do {                                                                       \
        M = 0;                                                                 \
        H0 = H1 = H2 = H3 = 0; T0 = T1 = T2 = T3 = 0;                          \
        Y0 = Y1 = Y2 = Y3 = 0;                                                 \
        if ((PG) < ngrp) {                                                     \
            int _b = 4 * (PG);                                                 \
            if (al4 && _b + 3 < E) {                                           \
                int4 _h = __ldg((const int4*)(head + _b));                     \
                int4 _t = __ldg((const int4*)(tail + _b));                     \
                int4 _y = __ldg((const int4*)(etype + _b));                    \
                H0 = _h.x; H1 = _h.y; H2 = _h.z; H3 = _h.w;                    \
                T0 = _t.x; T1 = _t.y; T2 = _t.z; T3 = _t.w;                    \
                Y0 = _y.x; Y1 = _y.y; Y2 = _y.z; Y3 = _y.w;                    \
                M = 0xF;                                                       \
            } else {                                                           \
                if (_b + 0 < E) { H0 = head[_b]; T0 = tail[_b]; Y0 = etype[_b]; M |= 1; } \
                if (_b + 1 < E) { H1 = head[_b+1]; T1 = tail[_b+1]; Y1 = etype[_b+1]; M |= 2; } \
                if (_b + 2 < E) { H2 = head[_b+2]; T2 = tail[_b+2]; Y2 = etype[_b+2]; M |= 4; } \
                if (_b + 3 < E) { H3 = head[_b+3]; T3 = tail[_b+3]; Y3 = etype[_b+3]; M |= 8; } \
            }                                                                  \
        }                                                                      \
    } while (0)

#define GATHER(M, T0, T1, T2, T3, H0, H1, H2, H3, A0, A1, A2, A3, Q0, Q1, Q2, Q3) \
    do {                                                                       \
        A0 = A1 = A2 = A3 = make_float2(0.f, 0.f);                             \
        Q0 = Q1 = Q2 = Q3 = make_float2(0.f, 0.f);                             \
        if ((M) & 1) { A0 = *(const float2*)(agg + (size_t)(T0) * EMB + 2 * lane); \
                       Q0 = *(const float2*)(Qm + (size_t)(H0) * EMB + 2 * lane); } \
        if ((M) & 2) { A1 = *(const float2*)(agg + (size_t)(T1) * EMB + 2 * lane); \
                       Q1 = *(const float2*)(Qm + (size_t)(H1) * EMB + 2 * lane); } \
        if ((M) & 4) { A2 = *(const float2*)(agg + (size_t)(T2) * EMB + 2 * lane); \
                       Q2 = *(const float2*)(Qm + (size_t)(H2) * EMB + 2 * lane); } \
        if ((M) & 8) { A3 = *(const float2*)(agg + (size_t)(T3) * EMB + 2 * lane); \
                       Q3 = *(const float2*)(Qm + (size_t)(H3) * EMB + 2 * lane); } \
    } while (0)

    // prologue: indices+gathers for group p, indices for p+nwarp
    {
        int tc0, tc1, tc2, tc3;
        LOAD_IDX(p, hc0, hc1, hc2, hc3, tc0, tc1, tc2, tc3, yc0, yc1, yc2, yc3, mc);
        GATHER(mc, tc0, tc1, tc2, tc3, hc0, hc1, hc2, hc3, a0, a1, a2c, a3, q0, q1, q2c, q3);
        LOAD_IDX(p + nwarp, hn0, hn1, hn2, hn3, tn0, tn1, tn2, tn3, yn0, yn1, yn2, yn3, mn);
    }

    int buf = 0;
    while (p < ngrp) {
        // ---- x = rel * a for 4 edges; stage duplicated to smem ----
        float2 r;
        r = *(const float2*)(srel + yc0 * EMB + 2 * lane);
        float2 x0 = make_float2(r.x * a0.x, r.y * a0.y);
        r = *(const float2*)(srel + yc1 * EMB + 2 * lane);
        float2 x1 = make_float2(r.x * a1.x, r.y * a1.y);
        r = *(const float2*)(srel + yc2 * EMB + 2 * lane);
        float2 x2 = make_float2(r.x * a2c.x, r.y * a2c.y);
        r = *(const float2*)(srel + yc3 * EMB + 2 * lane);
        float2 x3 = make_float2(r.x * a3.x, r.y * a3.y);
        *(float4*)(&sx[buf][w][0][4 * lane]) = make_float4(x0.x, x0.x, x0.y, x0.y);
        *(float4*)(&sx[buf][w][1][4 * lane]) = make_float4(x1.x, x1.x, x1.y, x1.y);
        *(float4*)(&sx[buf][w][2][4 * lane]) = make_float4(x2.x, x2.x, x2.y, x2.y);
        *(float4*)(&sx[buf][w][3][4 * lane]) = make_float4(x3.x, x3.x, x3.y, x3.y);

        // ---- gathers for next group (indices already resident) ----
        float2 na0, na1, na2, na3, nq0, nq1, nq2, nq3;
        GATHER(mn, tn0, tn1, tn2, tn3, hn0, hn1, hn2, hn3,
               na0, na1, na2, na3, nq0, nq1, nq2, nq3);

        // ---- indices for group p + 2*nwarp ----
        int h20, h21, h22, h23, t20, t21, t22, t23, y20, y21, y22, y23;
        unsigned m2;
        LOAD_IDX(p + 2 * nwarp, h20, h21, h22, h23, t20, t21, t22, t23,
                 y20, y21, y22, y23, m2);

        __syncwarp();

        // ---- quad matvec: 8 independent f32x2 chains ----
        const ulonglong2* xd0 = (const ulonglong2*)sx[buf][w][0];
        const ulonglong2* xd1 = (const ulonglong2*)sx[buf][w][1];
        const ulonglong2* xd2 = (const ulonglong2*)sx[buf][w][2];
        const ulonglong2* xd3 = (const ulonglong2*)sx[buf][w][3];
        unsigned long long y0a = 0, y0b = 0, y1a = 0, y1b = 0;
        unsigned long long y2a = 0, y2b = 0, y3a = 0, y3b = 0;
#pragma unroll
        for (int i = 0; i < 32; i++) {
            ulonglong2 v0 = xd0[i];
            ulonglong2 v1 = xd1[i];
            ulonglong2 v2 = xd2[i];
            ulonglong2 v3 = xd3[i];
            y0a = fma2(v0.x, K2[2 * i], y0a);
            y0b = fma2(v0.y, K2[2 * i + 1], y0b);
            y1a = fma2(v1.x, K2[2 * i], y1a);
            y1b = fma2(v1.y, K2[2 * i + 1], y1b);
            y2a = fma2(v2.x, K2[2 * i], y2a);
            y2b = fma2(v2.y, K2[2 * i + 1], y2b);
            y3a = fma2(v3.x, K2[2 * i], y3a);
            y3b = fma2(v3.y, K2[2 * i + 1], y3b);
        }
        float u0, u1, v0, v1;
        unpack2(y0a, u0, u1); unpack2(y0b, v0, v1);
        float p0 = q0.x * tanh_fast(u0 + v0) + q0.y * tanh_fast(u1 + v1);
        unpack2(y1a, u0, u1); unpack2(y1b, v0, v1);
        float p1 = q1.x * tanh_fast(u0 + v0) + q1.y * tanh_fast(u1 + v1);
        unpack2(y2a, u0, u1); unpack2(y2b, v0, v1);
        float p2 = q2c.x * tanh_fast(u0 + v0) + q2c.y * tanh_fast(u1 + v1);
        unpack2(y3a, u0, u1); unpack2(y3b, v0, v1);
        float p3 = q3.x * tanh_fast(u0 + v0) + q3.y * tanh_fast(u1 + v1);
#pragma unroll
        for (int o = 16; o; o >>= 1) {
            p0 += __shfl_xor_sync(0xffffffffu, p0, o);
            p1 += __shfl_xor_sync(0xffffffffu, p1, o);
            p2 += __shfl_xor_sync(0xffffffffu, p2, o);
            p3 += __shfl_xor_sync(0xffffffffu, p3, o);
        }
        float e0 = __expf(p0), e1 = __expf(p1), e2 = __expf(p2), e3 = __expf(p3);

        if (mc & 1)
            atomicAdd((float2*)(g_s + (size_t)hc0 * EMB + 2 * lane),
                      make_float2(e0 * x0.x, e0 * x0.y));
        if (mc & 2)
            atomicAdd((float2*)(g_s + (size_t)hc1 * EMB + 2 * lane),
                      make_float2(e1 * x1.x, e1 * x1.y));
        if (mc & 4)
            atomicAdd((float2*)(g_s + (size_t)hc2 * EMB + 2 * lane),
                      make_float2(e2 * x2.x, e2 * x2.y));
        if (mc & 8)
            atomicAdd((float2*)(g_s + (size_t)hc3 * EMB + 2 * lane),
                      make_float2(e3 * x3.x, e3 * x3.y));
        if (lane == 0 && (mc & 1)) atomicAdd(&g_denom[hc0], e0);
        if (lane == 1 && (mc & 2)) atomicAdd(&g_denom[hc1], e1);
        if (lane == 2 && (mc & 4)) atomicAdd(&g_denom[hc2], e2);
        if (lane == 3 && (mc & 8)) atomicAdd(&g_denom[hc3], e3);

        // ---- rotate pipeline ----
        hc0 = hn0; hc1 = hn1; hc2 = hn2; hc3 = hn3;
        yc0 = yn0; yc1 = yn1; yc2 = yn2; yc3 = yn3;
        mc = mn;
        a0 = na0; a1 = na1; a2c = na2; a3 = na3;
        q0 = nq0; q1 = nq1; q2c = nq2; q3 = nq3;
        hn0 = h20; hn1 = h21; hn2 = h22; hn3 = h23;
        tn0 = t20; tn1 = t21; tn2 = t22; tn3 = t23;
        yn0 = y20; yn1 = y21; yn2 = y22; yn3 = y23;
        mn = m2;
        p += nwarp;
        buf ^= 1;
    }
#undef LOAD_IDX
#undef GATHER
}

// ---------------------------------------------------------------------------
// agg = l2norm( (s/denom) / max(cnt,1) );  kg (+)= agg + entity_emb
__global__ void finalize_kernel(const float* __restrict__ ent_emb,
                                float* __restrict__ kg, int first, int N) {
    int lane = threadIdx.x & 31;
    int gw = (blockIdx.x * blockDim.x + threadIdx.x) >> 5;
    int nw = (gridDim.x * blockDim.x) >> 5;
    for (int ent = gw; ent < N; ent += nw) {
        float2 s2 = *(const float2*)(g_s + (size_t)ent * EMB + 2 * lane);
        float d = g_denom[ent];
        float c = fmaxf(g_cnt[ent], 1.0f);
        float inv = (d > 0.f) ? 1.0f / (d * c) : 0.0f;
        float a0 = s2.x * inv, a1 = s2.y * inv;
        float ss = a0 * a0 + a1 * a1;
#pragma unroll
        for (int o = 16; o; o >>= 1) ss += __shfl_xor_sync(0xffffffffu, ss, o);
        float sc = 1.0f / fmaxf(sqrtf(ss), 1e-12f);
        a0 *= sc; a1 *= sc;
        *(float2*)(g_agg + (size_t)ent * EMB + 2 * lane) = make_float2(a0, a1);
        float2 e2 = *(const float2*)(ent_emb + (size_t)ent * EMB + 2 * lane);
        float k0 = a0 + e2.x, k1 = a1 + e2.y;
        if (!first) {
            float2 kp = *(const float2*)(kg + (size_t)ent * EMB + 2 * lane);
            k0 += kp.x; k1 += kp.y;
        }
        *(float2*)(kg + (size_t)ent * EMB + 2 * lane) = make_float2(k0, k1);
    }
}

// ---------------------------------------------------------------------------
extern "C" void kernel_launch(void* const* d_in, const int* in_sizes, int n_in,
                              void* d_out, int out_size) {
    const float* ent      = (const float*)d_in[0];
    const float* edge_emb = (const float*)d_in[1];
    const float* qw       = (const float*)d_in[2];
    const float* kw       = (const float*)d_in[3];
    const int*   eidx     = (const int*)d_in[4];
    const int*   etype    = (const int*)d_in[5];
    int E = in_sizes[4] / 2;
    int N = in_sizes[0] / EMB;
    float* kg = (float*)d_out;
    const int* head = eidx;
    const int* tail = eidx + E;

    float* aggb = nullptr;
    cudaGetSymbolAddress((void**)&aggb, g_agg);
    float* qb = nullptr;
    cudaGetSymbolAddress((void**)&qb, g_q);

    const int TB = 256;
    const int G_EDGE = 304;
    const int G_PROJ = 304;
    const int G_LIGHT = 1024;

    // degree (constant across hops)
    zero_cnt_kernel<<<G_LIGHT, TB>>>(N);
    degree_kernel<<<G_LIGHT, TB>>>(head, E);

    // Q0 = entity_emb @ q_w
    qproj_kernel<<<G_PROJ, TB>>>(ent, qb, qw, N);

    // hop 0 (agg = entity_emb)
    zero_sd_kernel<<<G_LIGHT, TB>>>(N);
    edge_kernel<<<G_EDGE, TB>>>(ent, qb, kw, edge_emb, head, tail, etype, E);
    finalize_kernel<<<G_LIGHT, TB>>>(ent, kg, 1, N);

    // Q1 = agg @ q_w
    qproj_kernel<<<G_PROJ, TB>>>(aggb, qb, qw, N);

    // hop 1
    zero_sd_kernel<<<G_LIGHT, TB>>>(N);
    edge_kernel<<<G_EDGE, TB>>>(aggb, qb, kw, edge_emb, head, tail, etype, E);
    finalize_kernel<<<G_LIGHT, TB>>>(ent, kg, 0, N);
}

// round 15
// speedup vs baseline: 1.4631x; 1.4631x over previous
#include <cuda_runtime.h>
#include <cstdint>

#define NE_MAX 100000
#define EMB 64
#define NREL 32

// Scratch (allocation-free rule: device globals)
__device__ __align__(16) float g_s[NE_MAX * EMB];      // sum of e * x per head
__device__ __align__(16) float g_denom[NE_MAX];        // sum of e per head
__device__ __align__(16) float g_cnt[NE_MAX];          // out-degree (constant)
__device__ __align__(16) float g_agg[NE_MAX * EMB];    // current agg
__device__ __align__(16) float g_q[NE_MAX * EMB];      // Q = agg @ q_w

static __device__ __forceinline__ unsigned long long pack2(float a, float b) {
    unsigned long long r;
    asm("mov.b64 %0, {%1,%2};" : "=l"(r) : "f"(a), "f"(b));
    return r;
}
static __device__ __forceinline__ void unpack2(unsigned long long v, float& a, float& b) {
    asm("mov.b64 {%0,%1}, %2;" : "=f"(a), "=f"(b) : "l"(v));
}
static __device__ __forceinline__ unsigned long long fma2(unsigned long long a,
                                                          unsigned long long b,
                                                          unsigned long long c) {
    unsigned long long d;
    asm("fma.rn.f32x2 %0, %1, %2, %3;" : "=l"(d) : "l"(a), "l"(b), "l"(c));
    return d;
}
static __device__ __forceinline__ float tanh_fast(float x) {
    float y;
    asm("tanh.approx.f32 %0, %1;" : "=f"(y) : "f"(x));
    return y;
}
static __device__ __forceinline__ void bar64(int id) {
    asm volatile("bar.sync %0, 64;" :: "r"(id) : "memory");
}

// ---------------------------------------------------------------------------
__global__ void zero_sd_kernel(int N) {
    int i = blockIdx.x * blockDim.x + threadIdx.x;
    int st = gridDim.x * blockDim.x;
    float4* s4 = (float4*)g_s;
    int n4 = N * EMB / 4;
    for (int k = i; k < n4; k += st) s4[k] = make_float4(0.f, 0.f, 0.f, 0.f);
    float4* d4 = (float4*)g_denom;
    int m4 = (N + 3) / 4;
    for (int k = i; k < m4; k += st) d4[k] = make_float4(0.f, 0.f, 0.f, 0.f);
}

__global__ void zero_cnt_kernel(int N) {
    int i = blockIdx.x * blockDim.x + threadIdx.x;
    int st = gridDim.x * blockDim.x;
    float4* c4 = (float4*)g_cnt;
    int n4 = (N + 3) / 4;
    for (int k = i; k < n4; k += st) c4[k] = make_float4(0.f, 0.f, 0.f, 0.f);
}

__global__ void degree_kernel(const int* __restrict__ head, int E) {
    int i = blockIdx.x * blockDim.x + threadIdx.x;
    int st = gridDim.x * blockDim.x;
    for (; i < E; i += st) atomicAdd(&g_cnt[head[i]], 1.0f);
}

// ---------------------------------------------------------------------------
// dst[ent] = src[ent] @ W  (64x64), warp per entity, W register-resident.
__global__ void __launch_bounds__(256, 1) qproj_kernel(
    const float* __restrict__ src, float* __restrict__ dst,
    const float* __restrict__ W, int N) {
    __shared__ __align__(16) float sx[8][2 * EMB];
    int lane = threadIdx.x & 31, w = threadIdx.x >> 5;
    unsigned long long W2[EMB];
#pragma unroll
    for (int i = 0; i < EMB; i++) {
        float2 kv = *(const float2*)(W + i * EMB + 2 * lane);
        W2[i] = pack2(kv.x, kv.y);
    }
    int gw = blockIdx.x * 8 + w, nw = gridDim.x * 8;
    for (int ent = gw; ent < N; ent += nw) {
        float2 v = *(const float2*)(src + (size_t)ent * EMB + 2 * lane);
        *(float4*)(&sx[w][4 * lane]) = make_float4(v.x, v.x, v.y, v.y);
        __syncwarp();
        const ulonglong2* xd = (const ulonglong2*)sx[w];
        unsigned long long ya = 0ull, yb = 0ull;
#pragma unroll
        for (int i = 0; i < 32; i++) {
            ulonglong2 xv = xd[i];
            ya = fma2(xv.x, W2[2 * i], ya);
            yb = fma2(xv.y, W2[2 * i + 1], yb);
        }
        float y0a, y1a, y0b, y1b;
        unpack2(ya, y0a, y1a);
        unpack2(yb, y0b, y1b);
        __syncwarp();
        *(float2*)(dst + (size_t)ent * EMB + 2 * lane) =
            make_float2(y0a + y0b, y1a + y1b);
    }
}

// ---------------------------------------------------------------------------
// Fused edge pass, split-K warp pairs.
// A pair of warps (64 threads) processes 2 edges per iteration.
// Warp half s owns k_w rows [s*32, s*32+32) (64 regs) and "owns" edge s of the
// pair: it gathers a/q for edge s, stages x_s, and runs edge s's serial tail.
// Both warps compute half-K partial matvecs for BOTH edges; the cross partial
// is exchanged through shared memory with two named barriers (double-buffered).
// Registers ~115/thread -> 2 blocks/SM -> 4 warps/SMSP (2x round-8 occupancy).
__global__ void __launch_bounds__(256, 2) edge_kernel(
    const float* __restrict__ agg, const float* __restrict__ Qm,
    const float* __restrict__ kw, const float* __restrict__ edge_emb,
    const int* __restrict__ head, const int* __restrict__ tail,
    const int* __restrict__ etype, int E) {
    __shared__ __align__(16) float srel[NREL * EMB];                // 8 KB
    __shared__ __align__(16) float sx[2][4][2][2 * EMB];            // 8 KB
    __shared__ __align__(16) float spart[2][4][2][EMB];             // 4 KB
    int tid = threadIdx.x;
    for (int i = tid; i < NREL * EMB; i += 256) srel[i] = edge_emb[i];
    __syncthreads();

    const int lane = tid & 31;
    const int w = tid >> 5;
    const int pair = w >> 1;      // 0..3
    const int s = w & 1;          // which half / which edge of the pair
    const int barid = 1 + pair;

    // Half of k_w: rows [s*32, s*32+32), columns {2*lane, 2*lane+1}
    unsigned long long K2[32];
#pragma unroll
    for (int i = 0; i < 32; i++) {
        float2 kv = *(const float2*)(kw + (size_t)(s * 32 + i) * EMB + 2 * lane);
        K2[i] = pack2(kv.x, kv.y);
    }

    const int np = gridDim.x * 4;           // total pairs
    const int ngrp = (E + 1) >> 1;          // edge groups of 2
    int g = blockIdx.x * 4 + pair;

    // pipeline state (own edge only)
    int hc = 0, tyc = 0;
    bool vc = false;
    float2 ac = make_float2(0.f, 0.f), qc = make_float2(0.f, 0.f);
    int hn = 0, tn = 0, tyn = 0;
    bool vn = false;

    // prologue
    if (g < ngrp) {
        int e = 2 * g + s;
        if (e < E) {
            vc = true;
            hc = __ldg(head + e);
            int t = __ldg(tail + e);
            tyc = __ldg(etype + e);
            ac = *(const float2*)(agg + (size_t)t * EMB + 2 * lane);
            qc = *(const float2*)(Qm + (size_t)hc * EMB + 2 * lane);
        }
        int gn = g + np;
        if (gn < ngrp) {
            int en = 2 * gn + s;
            if (en < E) {
                vn = true;
                hn = __ldg(head + en);
                tn = __ldg(tail + en);
                tyn = __ldg(etype + en);
            }
        }
    }

    int buf = 0;
    while (g < ngrp) {
        // ---- stage x for own edge ----
        float2 r = *(const float2*)(srel + tyc * EMB + 2 * lane);
        float x0 = r.x * ac.x, x1 = r.y * ac.y;
        *(float4*)(&sx[buf][pair][s][4 * lane]) = make_float4(x0, x0, x1, x1);

        // ---- gathers for next group's own edge (indices resident) ----
        float2 an = make_float2(0.f, 0.f), qn = make_float2(0.f, 0.f);
        if (vn) {
            an = *(const float2*)(agg + (size_t)tn * EMB + 2 * lane);
            qn = *(const float2*)(Qm + (size_t)hn * EMB + 2 * lane);
        }
        // ---- indices for group g + 2*np ----
        int h2 = 0, t2 = 0, ty2 = 0;
        bool v2 = false;
        int g2 = g + 2 * np;
        if (g2 < ngrp) {
            int e2 = 2 * g2 + s;
            if (e2 < E) {
                v2 = true;
                h2 = __ldg(head + e2);
                t2 = __ldg(tail + e2);
                ty2 = __ldg(etype + e2);
            }
        }

        bar64(barid);  // x of both edges visible to the pair

        // ---- half-K partial matvec for BOTH edges (4 fma2 chains) ----
        // u64 view: element k duplicates x_k; my rows are k in [s*32, s*32+32)
        const ulonglong2* xd0 =
            (const ulonglong2*)sx[buf][pair][0] + 16 * s;
        const ulonglong2* xd1 =
            (const ulonglong2*)sx[buf][pair][1] + 16 * s;
        unsigned long long c0a = 0, c0b = 0, c1a = 0, c1b = 0;
#pragma unroll
        for (int j = 0; j < 8; j++) {
            ulonglong2 u0 = xd0[j];
            ulonglong2 u1 = xd1[j];
            ulonglong2 v0 = xd0[8 + j];
            ulonglong2 v1 = xd1[8 + j];
            c0a = fma2(u0.x, K2[2 * j], c0a);
            c0a = fma2(u0.y, K2[2 * j + 1], c0a);
            c1a = fma2(u1.x, K2[2 * j], c1a);
            c1a = fma2(u1.y, K2[2 * j + 1], c1a);
            c0b = fma2(v0.x, K2[16 + 2 * j], c0b);
            c0b = fma2(v0.y, K2[16 + 2 * j + 1], c0b);
            c1b = fma2(v1.x, K2[16 + 2 * j], c1b);
            c1b = fma2(v1.y, K2[16 + 2 * j + 1], c1b);
        }
        // fold own-edge partial (edge s) and cross partial (edge 1-s)
        float o0, o1, o2, o3, p0, p1, p2, p3;
        if (s == 0) {
            unpack2(c0a, o0, o1); unpack2(c0b, o2, o3);   // own = edge0
            unpack2(c1a, p0, p1); unpack2(c1b, p2, p3);   // cross = edge1
        } else {
            unpack2(c1a, o0, o1); unpack2(c1b, o2, o3);   // own = edge1
            unpack2(c0a, p0, p1); unpack2(c0b, p2, p3);   // cross = edge0
        }
        float own0 = o0 + o2, own1 = o1 + o3;
        // store cross partial for partner
        *(float2*)(&spart[buf][pair][1 - s][2 * lane]) =
            make_float2(p0 + p2, p1 + p3);

        bar64(barid);  // partials exchanged

        float2 po = *(const float2*)(&spart[buf][pair][s][2 * lane]);
        float y0 = own0 + po.x, y1 = own1 + po.y;
        float att = qc.x * tanh_fast(y0) + qc.y * tanh_fast(y1);
#pragma unroll
        for (int o = 16; o; o >>= 1) att += __shfl_xor_sync(0xffffffffu, att, o);
        float ew = __expf(att);

        if (vc) {
            atomicAdd((float2*)(g_s + (size_t)hc * EMB + 2 * lane),
                      make_float2(ew * x0, ew * x1));
            if (lane == 0) atomicAdd(&g_denom[hc], ew);
        }

        // ---- rotate pipeline ----
        hc = hn; tyc = tyn; vc = vn;
        ac = an; qc = qn;
        hn = h2; tn = t2; tyn = ty2; vn = v2;
        g += np;
        buf ^= 1;
    }
}

// ---------------------------------------------------------------------------
// agg = l2norm( (s/denom) / max(cnt,1) );  kg (+)= agg + entity_emb
__global__ void finalize_kernel(const float* __restrict__ ent_emb,
                                float* __restrict__ kg, int first, int N) {
    int lane = threadIdx.x & 31;
    int gw = (blockIdx.x * blockDim.x + threadIdx.x) >> 5;
    int nw = (gridDim.x * blockDim.x) >> 5;
    for (int ent = gw; ent < N; ent += nw) {
        float2 s2 = *(const float2*)(g_s + (size_t)ent * EMB + 2 * lane);
        float d = g_denom[ent];
        float c = fmaxf(g_cnt[ent], 1.0f);
        float inv = (d > 0.f) ? 1.0f / (d * c) : 0.0f;
        float a0 = s2.x * inv, a1 = s2.y * inv;
        float ss = a0 * a0 + a1 * a1;
#pragma unroll
        for (int o = 16; o; o >>= 1) ss += __shfl_xor_sync(0xffffffffu, ss, o);
        float sc = 1.0f / fmaxf(sqrtf(ss), 1e-12f);
        a0 *= sc; a1 *= sc;
        *(float2*)(g_agg + (size_t)ent * EMB + 2 * lane) = make_float2(a0, a1);
        float2 e2 = *(const float2*)(ent_emb + (size_t)ent * EMB + 2 * lane);
        float k0 = a0 + e2.x, k1 = a1 + e2.y;
        if (!first) {
            float2 kp = *(const float2*)(kg + (size_t)ent * EMB + 2 * lane);
            k0 += kp.x; k1 += kp.y;
        }
        *(float2*)(kg + (size_t)ent * EMB + 2 * lane) = make_float2(k0, k1);
    }
}

// ---------------------------------------------------------------------------
extern "C" void kernel_launch(void* const* d_in, const int* in_sizes, int n_in,
                              void* d_out, int out_size) {
    const float* ent      = (const float*)d_in[0];
    const float* edge_emb = (const float*)d_in[1];
    const float* qw       = (const float*)d_in[2];
    const float* kw       = (const float*)d_in[3];
    const int*   eidx     = (const int*)d_in[4];
    const int*   etype    = (const int*)d_in[5];
    int E = in_sizes[4] / 2;
    int N = in_sizes[0] / EMB;
    float* kg = (float*)d_out;
    const int* head = eidx;
    const int* tail = eidx + E;

    float* aggb = nullptr;
    cudaGetSymbolAddress((void**)&aggb, g_agg);
    float* qb = nullptr;
    cudaGetSymbolAddress((void**)&qb, g_q);

    const int TB = 256;
    const int G_EDGE = 304;
    const int G_PROJ = 304;
    const int G_LIGHT = 1024;

    // degree (constant across hops)
    zero_cnt_kernel<<<G_LIGHT, TB>>>(N);
    degree_kernel<<<G_LIGHT, TB>>>(head, E);

    // Q0 = entity_emb @ q_w
    qproj_kernel<<<G_PROJ, TB>>>(ent, qb, qw, N);

    // hop 0 (agg = entity_emb)
    zero_sd_kernel<<<G_LIGHT, TB>>>(N);
    edge_kernel<<<G_EDGE, TB>>>(ent, qb, kw, edge_emb, head, tail, etype, E);
    finalize_kernel<<<G_LIGHT, TB>>>(ent, kg, 1, N);

    // Q1 = agg @ q_w
    qproj_kernel<<<G_PROJ, TB>>>(aggb, qb, qw, N);

    // hop 1
    zero_sd_kernel<<<G_LIGHT, TB>>>(N);
    edge_kernel<<<G_EDGE, TB>>>(aggb, qb, kw, edge_emb, head, tail, etype, E);
    finalize_kernel<<<G_LIGHT, TB>>>(ent, kg, 0, N);
}